// round 15
// baseline (speedup 1.0000x reference)
#include <cuda_runtime.h>
#include <math.h>
#include <stdint.h>

#define S_DIM 1024
#define N_DIM 512
#define CM 64
#define CC 8
#define CZ 128
#define HH 8
#define NROWS (S_DIM*N_DIM)        // 524288
#define PDIM (S_DIM*CC)            // 8192

// ---- scratch ----
__device__ float g_G [(size_t)NROWS*CM];                 // gate, [s*N+i][hc]
__device__ float g_Vt[(size_t)HH*N_DIM*PDIM];            // v^T,  [h][j][p=s*8+c]  (tf32-rounded)
__device__ float g_WV[(size_t)HH*N_DIM*PDIM];            // wv,   [h][i][p]
__device__ float g_Wsm[(size_t)HH*N_DIM*N_DIM];          // softmax w [h][i][j] (tf32-rounded)

__device__ __forceinline__ float tf32r(float x){
    uint32_t u; asm("cvt.rna.tf32.f32 %0, %1;" : "=r"(u) : "f"(x)); return __uint_as_float(u);
}
__device__ __forceinline__ void mma16n8k8(float* c, const uint32_t* a, const uint32_t* b){
    asm volatile("mma.sync.aligned.m16n8k8.row.col.f32.tf32.tf32.f32 "
        "{%0,%1,%2,%3}, {%4,%5,%6,%7}, {%8,%9}, {%0,%1,%2,%3};"
        : "+f"(c[0]), "+f"(c[1]), "+f"(c[2]), "+f"(c[3])
        : "r"(a[0]), "r"(a[1]), "r"(a[2]), "r"(a[3]), "r"(b[0]), "r"(b[1]));
}
__device__ __forceinline__ uint32_t smem_u32(const void* p){
    uint32_t a; asm("{ .reg .u64 t; cvta.to.shared.u64 t, %1; cvt.u32.u64 %0, t; }" : "=r"(a) : "l"(p)); return a;
}
__device__ __forceinline__ void cpasync16(uint32_t saddr, const void* g){
    asm volatile("cp.async.ca.shared.global [%0], [%1], 16;" :: "r"(saddr), "l"(g));
}

// ============================================================
// K1: per 128-row tile: LN -> st; GEMM st @ [Wmv|Wmg] (mma tf32);
//     sigmoid gate -> g_G; v half tf32 -> g_Vt. (unchanged, 2 CTAs/SM)
// ============================================================
__global__ void __launch_bounds__(256,2) k1_mma(
    const float* __restrict__ m, const float* __restrict__ lng, const float* __restrict__ lnb,
    const float* __restrict__ Wmv, const float* __restrict__ Wmg)
{
    extern __shared__ float sh1[];
    float* st   = sh1;               // [128][68]
    float* sW   = sh1 + 128*68;      // [64][136]
    float* sout = sh1;               // [128][132] overlays after GEMM

    int tid = threadIdx.x, wid = tid >> 5, lane = tid & 31;
    int group = lane >> 2, tg = lane & 3;
    int wm = wid >> 2, wn = wid & 3;
    float gm0 = lng[lane], gm1 = lng[lane+32];
    float bt0 = lnb[lane], bt1 = lnb[lane+32];

    int rbase = blockIdx.x*128;
    int ss = rbase >> 9, ii0 = rbase & 511;

    {
        int wk = tid >> 2, wq = tid & 3;
        #pragma unroll
        for (int u = 0; u < 4; u++) {
            float4 a4 = *(const float4*)&Wmv[(size_t)wk*64 + wq*16 + u*4];
            float4 b4 = *(const float4*)&Wmg[(size_t)wk*64 + wq*16 + u*4];
            *(float4*)&sW[wk*136 + wq*16 + u*4] =
                make_float4(tf32r(a4.x),tf32r(a4.y),tf32r(a4.z),tf32r(a4.w));
            *(float4*)&sW[wk*136 + 64 + wq*16 + u*4] =
                make_float4(tf32r(b4.x),tf32r(b4.y),tf32r(b4.z),tf32r(b4.w));
        }
    }
    #pragma unroll 1
    for (int rr = 0; rr < 16; rr += 4) {
        float xs0[4], xs1[4], s[4], q[4];
        #pragma unroll
        for (int u = 0; u < 4; u++) {
            int row = wid*16 + rr + u;
            xs0[u] = m[(size_t)(rbase+row)*64 + lane];
            xs1[u] = m[(size_t)(rbase+row)*64 + 32 + lane];
            s[u] = xs0[u] + xs1[u];
            q[u] = xs0[u]*xs0[u] + xs1[u]*xs1[u];
        }
        #pragma unroll
        for (int o = 16; o > 0; o >>= 1) {
            #pragma unroll
            for (int u = 0; u < 4; u++) {
                s[u] += __shfl_xor_sync(0xffffffffu, s[u], o);
                q[u] += __shfl_xor_sync(0xffffffffu, q[u], o);
            }
        }
        #pragma unroll
        for (int u = 0; u < 4; u++) {
            int row = wid*16 + rr + u;
            float mean = s[u]*(1.0f/64.0f);
            float var  = q[u]*(1.0f/64.0f) - mean*mean;
            float rs = rsqrtf(var + 1e-5f);
            st[row*68 + lane]      = tf32r((xs0[u]-mean)*rs*gm0 + bt0);
            st[row*68 + 32 + lane] = tf32r((xs1[u]-mean)*rs*gm1 + bt1);
        }
    }
    __syncthreads();

    float acc[4][4][4] = {};
    #pragma unroll
    for (int ks = 0; ks < 8; ks++) {
        uint32_t af[4][4], bf[4][2];
        #pragma unroll
        for (int mt = 0; mt < 4; mt++) {
            const float* ap = st + (wm*64 + mt*16 + group)*68 + ks*8 + tg;
            af[mt][0] = __float_as_uint(ap[0]);
            af[mt][1] = __float_as_uint(ap[8*68]);
            af[mt][2] = __float_as_uint(ap[4]);
            af[mt][3] = __float_as_uint(ap[8*68 + 4]);
        }
        #pragma unroll
        for (int nt = 0; nt < 4; nt++) {
            const float* bp = sW + (ks*8 + tg)*136 + wn*32 + nt*8 + group;
            bf[nt][0] = __float_as_uint(bp[0]);
            bf[nt][1] = __float_as_uint(bp[4*136]);
        }
        #pragma unroll
        for (int mt = 0; mt < 4; mt++)
            #pragma unroll
            for (int nt = 0; nt < 4; nt++)
                mma16n8k8(acc[mt][nt], af[mt], bf[nt]);
    }
    __syncthreads();
    #pragma unroll
    for (int mt = 0; mt < 4; mt++) {
        int r1 = wm*64 + mt*16 + group;
        #pragma unroll
        for (int nt = 0; nt < 4; nt++) {
            int col = wn*32 + nt*8 + tg*2;
            *(float2*)&sout[r1*132 + col]     = make_float2(acc[mt][nt][0], acc[mt][nt][1]);
            *(float2*)&sout[(r1+8)*132 + col] = make_float2(acc[mt][nt][2], acc[mt][nt][3]);
        }
    }
    __syncthreads();

    #pragma unroll
    for (int u = 0; u < 8; u++) {
        int flat = u*256 + tid;
        int row = flat >> 4, c4 = (flat & 15)*4;
        float4 v = *(const float4*)&sout[row*132 + 64 + c4];
        float4 gv;
        gv.x = __fdividef(1.0f, 1.0f + __expf(-v.x));
        gv.y = __fdividef(1.0f, 1.0f + __expf(-v.y));
        gv.z = __fdividef(1.0f, 1.0f + __expf(-v.z));
        gv.w = __fdividef(1.0f, 1.0f + __expf(-v.w));
        *(float4*)&g_G[(size_t)(rbase+row)*64 + c4] = gv;
    }
    #pragma unroll
    for (int u = 0; u < 4; u++) {
        int pidx = u*256 + tid;
        int h = pidx >> 7, row = pidx & 127;
        float4 v0 = *(const float4*)&sout[row*132 + h*8];
        float4 v1 = *(const float4*)&sout[row*132 + h*8 + 4];
        size_t off = ((size_t)h*N_DIM + ii0 + row)*PDIM + ss*8;
        *(float4*)&g_Vt[off]     = make_float4(tf32r(v0.x),tf32r(v0.y),tf32r(v0.z),tf32r(v0.w));
        *(float4*)&g_Vt[off + 4] = make_float4(tf32r(v1.x),tf32r(v1.y),tf32r(v1.z),tf32r(v1.w));
    }
}

// ============================================================
// K2 fused: per block i: bias[h][j] = LN(z[i,j,:]) @ Wz for all j (smem),
// then softmax over j per h, tf32 -> g_Wsm. Kills the 16MB round-trip.
// ============================================================
__global__ void __launch_bounds__(256) k2_fused(
    const float* __restrict__ z, const float* __restrict__ lng, const float* __restrict__ lnb,
    const float* __restrict__ Wz)
{
    __shared__ float sWz[CZ*9];
    __shared__ float sb[HH][520];
    int tid = threadIdx.x, lane = tid & 31, warp = tid >> 5;
    int i = blockIdx.x;
    for (int idx = tid; idx < CZ*8; idx += 256) {
        int k = idx >> 3, h = idx & 7;
        sWz[k*9 + h] = Wz[idx];
    }
    float g0=lng[lane], g1=lng[lane+32], g2=lng[lane+64], g3=lng[lane+96];
    float b0=lnb[lane], b1=lnb[lane+32], b2=lnb[lane+64], b3=lnb[lane+96];
    __syncthreads();

    #pragma unroll 1
    for (int jj = warp; jj < N_DIM; jj += 8) {
        const float* zp = z + ((size_t)i*N_DIM + jj)*CZ;
        float x0 = zp[lane], x1 = zp[lane+32], x2 = zp[lane+64], x3 = zp[lane+96];
        float s = x0+x1+x2+x3;
        float q = x0*x0 + x1*x1 + x2*x2 + x3*x3;
        #pragma unroll
        for (int o = 16; o > 0; o >>= 1) {
            s += __shfl_xor_sync(0xffffffffu, s, o);
            q += __shfl_xor_sync(0xffffffffu, q, o);
        }
        float mean = s * (1.0f/128.0f);
        float var  = q * (1.0f/128.0f) - mean*mean;
        float rs = rsqrtf(var + 1e-5f);
        float n0 = (x0-mean)*rs*g0 + b0;
        float n1 = (x1-mean)*rs*g1 + b1;
        float n2 = (x2-mean)*rs*g2 + b2;
        float n3 = (x3-mean)*rs*g3 + b3;
        float ph[8];
        #pragma unroll
        for (int h = 0; h < 8; h++) {
            float pp = n0*sWz[lane*9+h] + n1*sWz[(lane+32)*9+h]
                     + n2*sWz[(lane+64)*9+h] + n3*sWz[(lane+96)*9+h];
            #pragma unroll
            for (int o = 16; o > 0; o >>= 1) pp += __shfl_xor_sync(0xffffffffu, pp, o);
            ph[h] = pp;
        }
        if (lane == 0) {
            #pragma unroll
            for (int h = 0; h < 8; h++) sb[h][jj] = ph[h];
        }
    }
    __syncthreads();

    // softmax over j: warp w owns h=w
    {
        int h = warp;
        float v[16];
        float mx = -1e30f;
        #pragma unroll
        for (int k = 0; k < 16; k++) { v[k] = sb[h][k*32 + lane]; mx = fmaxf(mx, v[k]); }
        #pragma unroll
        for (int o = 16; o > 0; o >>= 1) mx = fmaxf(mx, __shfl_xor_sync(0xffffffffu, mx, o));
        float sm = 0.0f;
        #pragma unroll
        for (int k = 0; k < 16; k++) { v[k] = __expf(v[k]-mx); sm += v[k]; }
        #pragma unroll
        for (int o = 16; o > 0; o >>= 1) sm += __shfl_xor_sync(0xffffffffu, sm, o);
        float inv = __fdividef(1.0f, sm);
        float* dst = g_Wsm + (size_t)h*N_DIM*N_DIM + (size_t)i*N_DIM;
        #pragma unroll
        for (int k = 0; k < 16; k++) dst[k*32 + lane] = tf32r(v[k]*inv);
    }
}

// ============================================================
// K3: mma.sync tf32 GEMM per head; 3-stage cp.async, ONE barrier/iter,
// 2 CTAs/SM (smem 107.5KB).
// ============================================================
__global__ void __launch_bounds__(256,2) k3_mma()
{
    extern __shared__ float sh3[];
    float* sAs = sh3;                 // 3 x [128][36]
    float* sBs = sh3 + 3*4608;        // 3 x [32][136]
    uint32_t aS = smem_u32(sAs), bS = smem_u32(sBs);

    int tid = threadIdx.x, wid = tid >> 5, lane = tid & 31;
    int group = lane >> 2, tg = lane & 3;
    int wm = wid >> 2, wn = wid & 3;
    int h  = blockIdx.z;
    int i0 = blockIdx.y * 128;
    int p0 = blockIdx.x * 128;
    const float* A = g_Wsm + (size_t)h*N_DIM*N_DIM;
    const float* B = g_Vt  + (size_t)h*N_DIM*PDIM;
    float*       C = g_WV  + (size_t)h*N_DIM*PDIM;

    int lr = tid >> 3, lc = (tid & 7)*4;

    // prologue: stages 0 and 1
    #pragma unroll
    for (int st2 = 0; st2 < 2; st2++) {
        int k0 = st2*32;
        uint32_t ao = aS + (uint32_t)(st2*4608*4);
        uint32_t bo = bS + (uint32_t)(st2*4352*4);
        #pragma unroll
        for (int u = 0; u < 4; u++)
            cpasync16(ao + (uint32_t)((lr + u*32)*36 + lc)*4, &A[(size_t)(i0+lr+u*32)*N_DIM + k0 + lc]);
        #pragma unroll
        for (int u = 0; u < 4; u++)
            cpasync16(bo + (uint32_t)(lr*136 + lc + u*32)*4, &B[(size_t)(k0+lr)*PDIM + p0 + lc + u*32]);
        asm volatile("cp.async.commit_group;");
    }

    float acc[4][4][4] = {};
    #pragma unroll 1
    for (int it = 0; it < 16; it++) {
        if (it < 15) asm volatile("cp.async.wait_group 1;");
        else         asm volatile("cp.async.wait_group 0;");
        __syncthreads();
        if (it + 2 < 16) {
            int k0 = (it+2)*32;
            int b = (it+2)%3;
            uint32_t ao = aS + (uint32_t)(b*4608*4);
            uint32_t bo = bS + (uint32_t)(b*4352*4);
            #pragma unroll
            for (int u = 0; u < 4; u++)
                cpasync16(ao + (uint32_t)((lr + u*32)*36 + lc)*4, &A[(size_t)(i0+lr+u*32)*N_DIM + k0 + lc]);
            #pragma unroll
            for (int u = 0; u < 4; u++)
                cpasync16(bo + (uint32_t)(lr*136 + lc + u*32)*4, &B[(size_t)(k0+lr)*PDIM + p0 + lc + u*32]);
            asm volatile("cp.async.commit_group;");
        }
        const float* as = sAs + (it%3)*4608;
        const float* bs = sBs + (it%3)*4352;
        #pragma unroll
        for (int ks = 0; ks < 4; ks++) {
            uint32_t af[4][4], bf[4][2];
            #pragma unroll
            for (int mt = 0; mt < 4; mt++) {
                const float* ap = as + (wm*64 + mt*16 + group)*36 + ks*8 + tg;
                af[mt][0] = __float_as_uint(ap[0]);
                af[mt][1] = __float_as_uint(ap[8*36]);
                af[mt][2] = __float_as_uint(ap[4]);
                af[mt][3] = __float_as_uint(ap[8*36 + 4]);
            }
            #pragma unroll
            for (int nt = 0; nt < 4; nt++) {
                const float* bp = bs + (ks*8 + tg)*136 + wn*32 + nt*8 + group;
                bf[nt][0] = __float_as_uint(bp[0]);
                bf[nt][1] = __float_as_uint(bp[4*136]);
            }
            #pragma unroll
            for (int mt = 0; mt < 4; mt++)
                #pragma unroll
                for (int nt = 0; nt < 4; nt++)
                    mma16n8k8(acc[mt][nt], af[mt], bf[nt]);
        }
    }

    #pragma unroll
    for (int mt = 0; mt < 4; mt++) {
        int row = i0 + wm*64 + mt*16 + group;
        #pragma unroll
        for (int nt = 0; nt < 4; nt++) {
            int col = p0 + wn*32 + nt*8 + tg*2;
            *(float2*)&C[(size_t)row*PDIM + col]     = make_float2(acc[mt][nt][0], acc[mt][nt][1]);
            *(float2*)&C[(size_t)(row+8)*PDIM + col] = make_float2(acc[mt][nt][2], acc[mt][nt][3]);
        }
    }
}

// ============================================================
// K45: fused gate/out-projection + SwiGLU transition.
// Restructured: 2 barriers/chunk, weight loads overlapped with compute.
// ============================================================
__global__ void __launch_bounds__(256,2) k45_mma(
    const float* __restrict__ m, const float* __restrict__ Wout,
    const float* __restrict__ lng, const float* __restrict__ lnb,
    const float* __restrict__ Wa, const float* __restrict__ Wb, const float* __restrict__ Wo,
    float* __restrict__ out)
{
    extern __shared__ float sh45[];
    float* stA  = sh45;              // [128][68]
    float* ovl  = sh45 + 128*68;     // overlay region: 11520 floats
    float* sx   = ovl;               // [128][68] (overlaps shh+swab, NOT swo)
    float* shh  = ovl;               // [128][36]
    float* swab = ovl + 128*36;      // [64][72]
    float* swo  = ovl + 128*36 + 64*72;  // [32][72]
    float* sWout= sh45 + 128*68 + 11520; // [64][72]

    int tid = threadIdx.x, wid = tid >> 5, lane = tid & 31;
    int group = lane >> 2, tg = lane & 3;
    int wm = wid >> 2, wn = wid & 3;
    int wm2 = wid >> 1, wn2 = wid & 1;
    float gm0 = lng[lane], gm1 = lng[lane+32];
    float bt0 = lnb[lane], bt1 = lnb[lane+32];
    int wk = tid >> 2, wq = tid & 3;
    int wk2 = tid >> 3, wq2 = tid & 7;

    auto loadWab = [&](int hcL){
        #pragma unroll
        for (int u = 0; u < 2; u++) {
            float4 a4 = *(const float4*)&Wa[(size_t)wk*256 + hcL*32 + wq*8 + u*4];
            float4 b4 = *(const float4*)&Wb[(size_t)wk*256 + hcL*32 + wq*8 + u*4];
            int base = wk*72 + wq*16 + u*8;
            swab[base+0] = tf32r(a4.x); swab[base+1] = tf32r(b4.x);
            swab[base+2] = tf32r(a4.y); swab[base+3] = tf32r(b4.y);
            swab[base+4] = tf32r(a4.z); swab[base+5] = tf32r(b4.z);
            swab[base+6] = tf32r(a4.w); swab[base+7] = tf32r(b4.w);
        }
    };
    auto loadWo = [&](int hcL){
        #pragma unroll
        for (int u = 0; u < 2; u++) {
            float4 o4 = *(const float4*)&Wo[(size_t)(hcL*32 + wk2)*64 + wq2*8 + u*4];
            *(float4*)&swo[wk2*72 + wq2*8 + u*4] =
                make_float4(tf32r(o4.x), tf32r(o4.y), tf32r(o4.z), tf32r(o4.w));
        }
    };

    #pragma unroll
    for (int u = 0; u < 4; u++) {
        float4 w4 = *(const float4*)&Wout[(size_t)wk*64 + wq*16 + u*4];
        *(float4*)&sWout[wk*72 + wq*16 + u*4] =
            make_float4(tf32r(w4.x),tf32r(w4.y),tf32r(w4.z),tf32r(w4.w));
    }

    for (int tile = blockIdx.x; tile < NROWS/128; tile += gridDim.x) {
        int rbase = tile*128;
        int ss = rbase >> 9, ii0 = rbase & 511;

        // ---- 1. gated product -> stA (tf32) ----
        #pragma unroll
        for (int i = 0; i < 8; i++) {
            int flat4 = i*256 + tid;
            int row = flat4 >> 4, c4 = flat4 & 15;
            int k0 = c4*4; int hh = k0 >> 3, cc = k0 & 7;
            float4 g4 = *(const float4*)&g_G[(size_t)(rbase+row)*64 + k0];
            float4 w4 = *(const float4*)&g_WV[((size_t)hh*N_DIM + ii0 + row)*PDIM + ss*8 + cc];
            *(float4*)&stA[row*68 + k0] = make_float4(
                tf32r(g4.x*w4.x), tf32r(g4.y*w4.y), tf32r(g4.z*w4.z), tf32r(g4.w*w4.w));
        }
        __syncthreads();

        // ---- 2. acc2 = stA @ Wout + m (= out, in regs) ----
        float acc2[2][4][4] = {};
        #pragma unroll
        for (int ks = 0; ks < 8; ks++) {
            uint32_t af[2][4], bf[4][2];
            #pragma unroll
            for (int mt = 0; mt < 2; mt++) {
                const float* ap = stA + (wm2*32 + mt*16 + group)*68 + ks*8 + tg;
                af[mt][0] = __float_as_uint(ap[0]);
                af[mt][1] = __float_as_uint(ap[8*68]);
                af[mt][2] = __float_as_uint(ap[4]);
                af[mt][3] = __float_as_uint(ap[8*68 + 4]);
            }
            #pragma unroll
            for (int nt = 0; nt < 4; nt++) {
                const float* bp = sWout + (ks*8 + tg)*72 + wn2*32 + nt*8 + group;
                bf[nt][0] = __float_as_uint(bp[0]);
                bf[nt][1] = __float_as_uint(bp[4*72]);
            }
            #pragma unroll
            for (int mt = 0; mt < 2; mt++)
                #pragma unroll
                for (int nt = 0; nt < 4; nt++)
                    mma16n8k8(acc2[mt][nt], af[mt], bf[nt]);
        }
        #pragma unroll
        for (int mt = 0; mt < 2; mt++) {
            int row = rbase + wm2*32 + mt*16 + group;
            #pragma unroll
            for (int nt = 0; nt < 4; nt++) {
                int col = wn2*32 + nt*8 + tg*2;
                float2 m0 = *(const float2*)&m[(size_t)row*64 + col];
                acc2[mt][nt][0] += m0.x; acc2[mt][nt][1] += m0.y;
                float2 m1 = *(const float2*)&m[(size_t)(row+8)*64 + col];
                acc2[mt][nt][2] += m1.x; acc2[mt][nt][3] += m1.y;
            }
        }

        // ---- 3. acc2 -> sx for LN ----
        #pragma unroll
        for (int mt = 0; mt < 2; mt++) {
            int r1 = wm2*32 + mt*16 + group;
            #pragma unroll
            for (int nt = 0; nt < 4; nt++) {
                int col = wn2*32 + nt*8 + tg*2;
                *(float2*)&sx[r1*68 + col]     = make_float2(acc2[mt][nt][0], acc2[mt][nt][1]);
                *(float2*)&sx[(r1+8)*68 + col] = make_float2(acc2[mt][nt][2], acc2[mt][nt][3]);
            }
        }
        __syncthreads();
        loadWo(0);   // overlaps LN; swo disjoint from sx, prev readers done

        // ---- 4. LN(sx) -> stA (tf32) ----
        #pragma unroll 1
        for (int rr = 0; rr < 16; rr += 4) {
            float xs0[4], xs1[4], s[4], q[4];
            #pragma unroll
            for (int u = 0; u < 4; u++) {
                int row = wid*16 + rr + u;
                xs0[u] = sx[row*68 + lane];
                xs1[u] = sx[row*68 + 32 + lane];
                s[u] = xs0[u] + xs1[u];
                q[u] = xs0[u]*xs0[u] + xs1[u]*xs1[u];
            }
            #pragma unroll
            for (int o = 16; o > 0; o >>= 1) {
                #pragma unroll
                for (int u = 0; u < 4; u++) {
                    s[u] += __shfl_xor_sync(0xffffffffu, s[u], o);
                    q[u] += __shfl_xor_sync(0xffffffffu, q[u], o);
                }
            }
            #pragma unroll
            for (int u = 0; u < 4; u++) {
                int row = wid*16 + rr + u;
                float mean = s[u]*(1.0f/64.0f);
                float var  = q[u]*(1.0f/64.0f) - mean*mean;
                float rs = rsqrtf(var + 1e-5f);
                stA[row*68 + lane]      = tf32r((xs0[u]-mean)*rs*gm0 + bt0);
                stA[row*68 + 32 + lane] = tf32r((xs1[u]-mean)*rs*gm1 + bt1);
            }
        }
        __syncthreads();   // stA visible, sx dead
        loadWab(0);
        __syncthreads();   // swab(0) visible (swo(0) also)

        // ---- 5. transition: 8 chunks, 2 barriers each ----
        #pragma unroll 1
        for (int hc = 0; hc < 8; hc++) {
            // GEMM1: stA[128x64] @ wab (32 hidden, interleaved)
            float acc1[4][2][4] = {};
            #pragma unroll
            for (int ks = 0; ks < 8; ks++) {
                uint32_t af[4][4], bf[2][2];
                #pragma unroll
                for (int mt = 0; mt < 4; mt++) {
                    const float* ap = stA + (wm*64 + mt*16 + group)*68 + ks*8 + tg;
                    af[mt][0] = __float_as_uint(ap[0]);
                    af[mt][1] = __float_as_uint(ap[8*68]);
                    af[mt][2] = __float_as_uint(ap[4]);
                    af[mt][3] = __float_as_uint(ap[8*68 + 4]);
                }
                #pragma unroll
                for (int nt = 0; nt < 2; nt++) {
                    const float* bp = swab + (ks*8 + tg)*72 + wn*16 + nt*8 + group;
                    bf[nt][0] = __float_as_uint(bp[0]);
                    bf[nt][1] = __float_as_uint(bp[4*72]);
                }
                #pragma unroll
                for (int mt = 0; mt < 4; mt++)
                    #pragma unroll
                    for (int nt = 0; nt < 2; nt++)
                        mma16n8k8(acc1[mt][nt], af[mt], bf[nt]);
            }
            // SiLU(a)*b -> shh
            #pragma unroll
            for (int mt = 0; mt < 4; mt++) {
                int r1 = wm*64 + mt*16 + group;
                #pragma unroll
                for (int nt = 0; nt < 2; nt++) {
                    int hcol = wn*8 + nt*4 + tg;
                    float a0 = acc1[mt][nt][0], b0v = acc1[mt][nt][1];
                    float a1 = acc1[mt][nt][2], b1v = acc1[mt][nt][3];
                    float h0 = __fdividef(a0, 1.0f + __expf(-a0)) * b0v;
                    float h1 = __fdividef(a1, 1.0f + __expf(-a1)) * b1v;
                    shh[r1*36 + hcol]      = tf32r(h0);
                    shh[(r1+8)*36 + hcol]  = tf32r(h1);
                }
            }
            __syncthreads();                  // (c): shh visible; swab free
            if (hc < 7) loadWab(hc+1);        // overlaps GEMM2
            // GEMM2: shh[128x32] @ swo[32x64] -> acc2
            #pragma unroll
            for (int ks = 0; ks < 4; ks++) {
                uint32_t af[2][4], bf[4][2];
                #pragma unroll
                for (int mt = 0; mt < 2; mt++) {
                    const float* ap = shh + (wm2*32 + mt*16 + group)*36 + ks*8 + tg;
                    af[mt][0] = __float_as_uint(ap[0]);
                    af[mt][1] = __float_as_uint(ap[8*36]);
                    af[mt][2] = __float_as_uint(ap[4]);
                    af[mt][3] = __float_as_uint(ap[8*36 + 4]);
                }
                #pragma unroll
                for (int nt = 0; nt < 4; nt++) {
                    const float* bp = swo + (ks*8 + tg)*72 + wn2*32 + nt*8 + group;
                    bf[nt][0] = __float_as_uint(bp[0]);
                    bf[nt][1] = __float_as_uint(bp[4*72]);
                }
                #pragma unroll
                for (int mt = 0; mt < 2; mt++)
                    #pragma unroll
                    for (int nt = 0; nt < 4; nt++)
                        mma16n8k8(acc2[mt][nt], af[mt], bf[nt]);
            }
            __syncthreads();                  // (a'): GEMM2 done; shh/swo free
            if (hc < 7) loadWo(hc+1);         // overlaps next GEMM1
        }
        // ---- 6. final store ----
        #pragma unroll
        for (int mt = 0; mt < 2; mt++) {
            int row = rbase + wm2*32 + mt*16 + group;
            #pragma unroll
            for (int nt = 0; nt < 4; nt++) {
                int col = wn2*32 + nt*8 + tg*2;
                *(float2*)&out[(size_t)row*64 + col] =
                    make_float2(acc2[mt][nt][0], acc2[mt][nt][1]);
                *(float2*)&out[(size_t)(row+8)*64 + col] =
                    make_float2(acc2[mt][nt][2], acc2[mt][nt][3]);
            }
        }
        // no tile-end barrier needed: (a') of hc=7 orders all smem reuse
    }
}

// ============================================================
extern "C" void kernel_launch(void* const* d_in, const int* in_sizes, int n_in,
                              void* d_out, int out_size) {
    const float* m    = (const float*)d_in[0];
    const float* z    = (const float*)d_in[1];
    const float* lnmg = (const float*)d_in[2];
    const float* lnmb = (const float*)d_in[3];
    const float* Wmv  = (const float*)d_in[4];
    const float* lnzg = (const float*)d_in[5];
    const float* lnzb = (const float*)d_in[6];
    const float* Wz   = (const float*)d_in[7];
    const float* Wmg  = (const float*)d_in[8];
    const float* Wout = (const float*)d_in[9];
    const float* lntg = (const float*)d_in[10];
    const float* lntb = (const float*)d_in[11];
    const float* Wa   = (const float*)d_in[12];
    const float* Wb   = (const float*)d_in[13];
    const float* Wo   = (const float*)d_in[14];
    float* out = (float*)d_out;

    const int k1_smem = (128*68 + 64*136) * 4;       // 69,632 B
    cudaFuncSetAttribute(k1_mma, cudaFuncAttributeMaxDynamicSharedMemorySize, k1_smem);
    k1_mma<<<NROWS/128, 256, k1_smem>>>(m, lnmg, lnmb, Wmv, Wmg);

    k2_fused<<<N_DIM, 256>>>(z, lnzg, lnzb, Wz);

    const int k3_smem = 3*(4608 + 4352) * 4;         // 107,520 B
    cudaFuncSetAttribute(k3_mma, cudaFuncAttributeMaxDynamicSharedMemorySize, k3_smem);
    k3_mma<<<dim3(PDIM/128, N_DIM/128, HH), 256, k3_smem>>>();

    const int k45_smem = (128*68 + 11520 + 64*72) * 4;   // 99,328 B
    cudaFuncSetAttribute(k45_mma, cudaFuncAttributeMaxDynamicSharedMemorySize, k45_smem);
    k45_mma<<<296, 256, k45_smem>>>(m, Wout, lntg, lntb, Wa, Wb, Wo, out);
    (void)in_sizes; (void)n_in; (void)out_size;
}

// round 16
// speedup vs baseline: 1.0037x; 1.0037x over previous
#include <cuda_runtime.h>
#include <math.h>
#include <stdint.h>

#define S_DIM 1024
#define N_DIM 512
#define CM 64
#define CC 8
#define CZ 128
#define HH 8
#define NROWS (S_DIM*N_DIM)        // 524288
#define PDIM (S_DIM*CC)            // 8192

// ---- scratch ----
__device__ float g_G [(size_t)NROWS*CM];                 // gate, [s*N+i][hc]
__device__ float g_Vt[(size_t)HH*N_DIM*PDIM];            // v^T,  [h][j][p=s*8+c]  (tf32-rounded)
__device__ float g_WV[(size_t)HH*N_DIM*PDIM];            // wv,   [h][i][p]
__device__ float g_Wsm[(size_t)HH*N_DIM*N_DIM];          // softmax w [h][i][j] (tf32-rounded)

__device__ __forceinline__ float tf32r(float x){
    uint32_t u; asm("cvt.rna.tf32.f32 %0, %1;" : "=r"(u) : "f"(x)); return __uint_as_float(u);
}
__device__ __forceinline__ void mma16n8k8(float* c, const uint32_t* a, const uint32_t* b){
    asm volatile("mma.sync.aligned.m16n8k8.row.col.f32.tf32.tf32.f32 "
        "{%0,%1,%2,%3}, {%4,%5,%6,%7}, {%8,%9}, {%0,%1,%2,%3};"
        : "+f"(c[0]), "+f"(c[1]), "+f"(c[2]), "+f"(c[3])
        : "r"(a[0]), "r"(a[1]), "r"(a[2]), "r"(a[3]), "r"(b[0]), "r"(b[1]));
}
__device__ __forceinline__ uint32_t smem_u32(const void* p){
    uint32_t a; asm("{ .reg .u64 t; cvta.to.shared.u64 t, %1; cvt.u32.u64 %0, t; }" : "=r"(a) : "l"(p)); return a;
}
__device__ __forceinline__ void cpasync16(uint32_t saddr, const void* g){
    asm volatile("cp.async.ca.shared.global [%0], [%1], 16;" :: "r"(saddr), "l"(g));
}

// ============================================================
// K1: per 128-row tile: LN -> st; GEMM st @ [Wmv|Wmg] (mma tf32);
//     sigmoid gate -> g_G; v half tf32 -> g_Vt. (unchanged, 2 CTAs/SM)
// ============================================================
__global__ void __launch_bounds__(256,2) k1_mma(
    const float* __restrict__ m, const float* __restrict__ lng, const float* __restrict__ lnb,
    const float* __restrict__ Wmv, const float* __restrict__ Wmg)
{
    extern __shared__ float sh1[];
    float* st   = sh1;               // [128][68]
    float* sW   = sh1 + 128*68;      // [64][136]
    float* sout = sh1;               // [128][132] overlays after GEMM

    int tid = threadIdx.x, wid = tid >> 5, lane = tid & 31;
    int group = lane >> 2, tg = lane & 3;
    int wm = wid >> 2, wn = wid & 3;
    float gm0 = lng[lane], gm1 = lng[lane+32];
    float bt0 = lnb[lane], bt1 = lnb[lane+32];

    int rbase = blockIdx.x*128;
    int ss = rbase >> 9, ii0 = rbase & 511;

    {
        int wk = tid >> 2, wq = tid & 3;
        #pragma unroll
        for (int u = 0; u < 4; u++) {
            float4 a4 = *(const float4*)&Wmv[(size_t)wk*64 + wq*16 + u*4];
            float4 b4 = *(const float4*)&Wmg[(size_t)wk*64 + wq*16 + u*4];
            *(float4*)&sW[wk*136 + wq*16 + u*4] =
                make_float4(tf32r(a4.x),tf32r(a4.y),tf32r(a4.z),tf32r(a4.w));
            *(float4*)&sW[wk*136 + 64 + wq*16 + u*4] =
                make_float4(tf32r(b4.x),tf32r(b4.y),tf32r(b4.z),tf32r(b4.w));
        }
    }
    #pragma unroll 1
    for (int rr = 0; rr < 16; rr += 4) {
        float xs0[4], xs1[4], s[4], q[4];
        #pragma unroll
        for (int u = 0; u < 4; u++) {
            int row = wid*16 + rr + u;
            xs0[u] = m[(size_t)(rbase+row)*64 + lane];
            xs1[u] = m[(size_t)(rbase+row)*64 + 32 + lane];
            s[u] = xs0[u] + xs1[u];
            q[u] = xs0[u]*xs0[u] + xs1[u]*xs1[u];
        }
        #pragma unroll
        for (int o = 16; o > 0; o >>= 1) {
            #pragma unroll
            for (int u = 0; u < 4; u++) {
                s[u] += __shfl_xor_sync(0xffffffffu, s[u], o);
                q[u] += __shfl_xor_sync(0xffffffffu, q[u], o);
            }
        }
        #pragma unroll
        for (int u = 0; u < 4; u++) {
            int row = wid*16 + rr + u;
            float mean = s[u]*(1.0f/64.0f);
            float var  = q[u]*(1.0f/64.0f) - mean*mean;
            float rs = rsqrtf(var + 1e-5f);
            st[row*68 + lane]      = tf32r((xs0[u]-mean)*rs*gm0 + bt0);
            st[row*68 + 32 + lane] = tf32r((xs1[u]-mean)*rs*gm1 + bt1);
        }
    }
    __syncthreads();

    float acc[4][4][4] = {};
    #pragma unroll
    for (int ks = 0; ks < 8; ks++) {
        uint32_t af[4][4], bf[4][2];
        #pragma unroll
        for (int mt = 0; mt < 4; mt++) {
            const float* ap = st + (wm*64 + mt*16 + group)*68 + ks*8 + tg;
            af[mt][0] = __float_as_uint(ap[0]);
            af[mt][1] = __float_as_uint(ap[8*68]);
            af[mt][2] = __float_as_uint(ap[4]);
            af[mt][3] = __float_as_uint(ap[8*68 + 4]);
        }
        #pragma unroll
        for (int nt = 0; nt < 4; nt++) {
            const float* bp = sW + (ks*8 + tg)*136 + wn*32 + nt*8 + group;
            bf[nt][0] = __float_as_uint(bp[0]);
            bf[nt][1] = __float_as_uint(bp[4*136]);
        }
        #pragma unroll
        for (int mt = 0; mt < 4; mt++)
            #pragma unroll
            for (int nt = 0; nt < 4; nt++)
                mma16n8k8(acc[mt][nt], af[mt], bf[nt]);
    }
    __syncthreads();
    #pragma unroll
    for (int mt = 0; mt < 4; mt++) {
        int r1 = wm*64 + mt*16 + group;
        #pragma unroll
        for (int nt = 0; nt < 4; nt++) {
            int col = wn*32 + nt*8 + tg*2;
            *(float2*)&sout[r1*132 + col]     = make_float2(acc[mt][nt][0], acc[mt][nt][1]);
            *(float2*)&sout[(r1+8)*132 + col] = make_float2(acc[mt][nt][2], acc[mt][nt][3]);
        }
    }
    __syncthreads();

    #pragma unroll
    for (int u = 0; u < 8; u++) {
        int flat = u*256 + tid;
        int row = flat >> 4, c4 = (flat & 15)*4;
        float4 v = *(const float4*)&sout[row*132 + 64 + c4];
        float4 gv;
        gv.x = __fdividef(1.0f, 1.0f + __expf(-v.x));
        gv.y = __fdividef(1.0f, 1.0f + __expf(-v.y));
        gv.z = __fdividef(1.0f, 1.0f + __expf(-v.z));
        gv.w = __fdividef(1.0f, 1.0f + __expf(-v.w));
        *(float4*)&g_G[(size_t)(rbase+row)*64 + c4] = gv;
    }
    #pragma unroll
    for (int u = 0; u < 4; u++) {
        int pidx = u*256 + tid;
        int h = pidx >> 7, row = pidx & 127;
        float4 v0 = *(const float4*)&sout[row*132 + h*8];
        float4 v1 = *(const float4*)&sout[row*132 + h*8 + 4];
        size_t off = ((size_t)h*N_DIM + ii0 + row)*PDIM + ss*8;
        *(float4*)&g_Vt[off]     = make_float4(tf32r(v0.x),tf32r(v0.y),tf32r(v0.z),tf32r(v0.w));
        *(float4*)&g_Vt[off + 4] = make_float4(tf32r(v1.x),tf32r(v1.y),tf32r(v1.z),tf32r(v1.w));
    }
}

// ============================================================
// K2 fused: per block i: LN+proj for all j, softmax per h, tf32 out.
// (kept from R15)
// ============================================================
__global__ void __launch_bounds__(256) k2_fused(
    const float* __restrict__ z, const float* __restrict__ lng, const float* __restrict__ lnb,
    const float* __restrict__ Wz)
{
    __shared__ float sWz[CZ*9];
    __shared__ float sb[HH][520];
    int tid = threadIdx.x, lane = tid & 31, warp = tid >> 5;
    int i = blockIdx.x;
    for (int idx = tid; idx < CZ*8; idx += 256) {
        int k = idx >> 3, h = idx & 7;
        sWz[k*9 + h] = Wz[idx];
    }
    float g0=lng[lane], g1=lng[lane+32], g2=lng[lane+64], g3=lng[lane+96];
    float b0=lnb[lane], b1=lnb[lane+32], b2=lnb[lane+64], b3=lnb[lane+96];
    __syncthreads();

    #pragma unroll 1
    for (int jj = warp; jj < N_DIM; jj += 8) {
        const float* zp = z + ((size_t)i*N_DIM + jj)*CZ;
        float x0 = zp[lane], x1 = zp[lane+32], x2 = zp[lane+64], x3 = zp[lane+96];
        float s = x0+x1+x2+x3;
        float q = x0*x0 + x1*x1 + x2*x2 + x3*x3;
        #pragma unroll
        for (int o = 16; o > 0; o >>= 1) {
            s += __shfl_xor_sync(0xffffffffu, s, o);
            q += __shfl_xor_sync(0xffffffffu, q, o);
        }
        float mean = s * (1.0f/128.0f);
        float var  = q * (1.0f/128.0f) - mean*mean;
        float rs = rsqrtf(var + 1e-5f);
        float n0 = (x0-mean)*rs*g0 + b0;
        float n1 = (x1-mean)*rs*g1 + b1;
        float n2 = (x2-mean)*rs*g2 + b2;
        float n3 = (x3-mean)*rs*g3 + b3;
        float ph[8];
        #pragma unroll
        for (int h = 0; h < 8; h++) {
            float pp = n0*sWz[lane*9+h] + n1*sWz[(lane+32)*9+h]
                     + n2*sWz[(lane+64)*9+h] + n3*sWz[(lane+96)*9+h];
            #pragma unroll
            for (int o = 16; o > 0; o >>= 1) pp += __shfl_xor_sync(0xffffffffu, pp, o);
            ph[h] = pp;
        }
        if (lane == 0) {
            #pragma unroll
            for (int h = 0; h < 8; h++) sb[h][jj] = ph[h];
        }
    }
    __syncthreads();

    {
        int h = warp;
        float v[16];
        float mx = -1e30f;
        #pragma unroll
        for (int k = 0; k < 16; k++) { v[k] = sb[h][k*32 + lane]; mx = fmaxf(mx, v[k]); }
        #pragma unroll
        for (int o = 16; o > 0; o >>= 1) mx = fmaxf(mx, __shfl_xor_sync(0xffffffffu, mx, o));
        float sm = 0.0f;
        #pragma unroll
        for (int k = 0; k < 16; k++) { v[k] = __expf(v[k]-mx); sm += v[k]; }
        #pragma unroll
        for (int o = 16; o > 0; o >>= 1) sm += __shfl_xor_sync(0xffffffffu, sm, o);
        float inv = __fdividef(1.0f, sm);
        float* dst = g_Wsm + (size_t)h*N_DIM*N_DIM + (size_t)i*N_DIM;
        #pragma unroll
        for (int k = 0; k < 16; k++) dst[k*32 + lane] = tf32r(v[k]*inv);
    }
}

// ============================================================
// K3: mma.sync tf32 GEMM per head; 3-stage cp.async, one barrier/iter.
// (kept from R15)
// ============================================================
__global__ void __launch_bounds__(256,2) k3_mma()
{
    extern __shared__ float sh3[];
    float* sAs = sh3;                 // 3 x [128][36]
    float* sBs = sh3 + 3*4608;        // 3 x [32][136]
    uint32_t aS = smem_u32(sAs), bS = smem_u32(sBs);

    int tid = threadIdx.x, wid = tid >> 5, lane = tid & 31;
    int group = lane >> 2, tg = lane & 3;
    int wm = wid >> 2, wn = wid & 3;
    int h  = blockIdx.z;
    int i0 = blockIdx.y * 128;
    int p0 = blockIdx.x * 128;
    const float* A = g_Wsm + (size_t)h*N_DIM*N_DIM;
    const float* B = g_Vt  + (size_t)h*N_DIM*PDIM;
    float*       C = g_WV  + (size_t)h*N_DIM*PDIM;

    int lr = tid >> 3, lc = (tid & 7)*4;

    #pragma unroll
    for (int st2 = 0; st2 < 2; st2++) {
        int k0 = st2*32;
        uint32_t ao = aS + (uint32_t)(st2*4608*4);
        uint32_t bo = bS + (uint32_t)(st2*4352*4);
        #pragma unroll
        for (int u = 0; u < 4; u++)
            cpasync16(ao + (uint32_t)((lr + u*32)*36 + lc)*4, &A[(size_t)(i0+lr+u*32)*N_DIM + k0 + lc]);
        #pragma unroll
        for (int u = 0; u < 4; u++)
            cpasync16(bo + (uint32_t)(lr*136 + lc + u*32)*4, &B[(size_t)(k0+lr)*PDIM + p0 + lc + u*32]);
        asm volatile("cp.async.commit_group;");
    }

    float acc[4][4][4] = {};
    #pragma unroll 1
    for (int it = 0; it < 16; it++) {
        if (it < 15) asm volatile("cp.async.wait_group 1;");
        else         asm volatile("cp.async.wait_group 0;");
        __syncthreads();
        if (it + 2 < 16) {
            int k0 = (it+2)*32;
            int b = (it+2)%3;
            uint32_t ao = aS + (uint32_t)(b*4608*4);
            uint32_t bo = bS + (uint32_t)(b*4352*4);
            #pragma unroll
            for (int u = 0; u < 4; u++)
                cpasync16(ao + (uint32_t)((lr + u*32)*36 + lc)*4, &A[(size_t)(i0+lr+u*32)*N_DIM + k0 + lc]);
            #pragma unroll
            for (int u = 0; u < 4; u++)
                cpasync16(bo + (uint32_t)(lr*136 + lc + u*32)*4, &B[(size_t)(k0+lr)*PDIM + p0 + lc + u*32]);
            asm volatile("cp.async.commit_group;");
        }
        const float* as = sAs + (it%3)*4608;
        const float* bs = sBs + (it%3)*4352;
        #pragma unroll
        for (int ks = 0; ks < 4; ks++) {
            uint32_t af[4][4], bf[4][2];
            #pragma unroll
            for (int mt = 0; mt < 4; mt++) {
                const float* ap = as + (wm*64 + mt*16 + group)*36 + ks*8 + tg;
                af[mt][0] = __float_as_uint(ap[0]);
                af[mt][1] = __float_as_uint(ap[8*36]);
                af[mt][2] = __float_as_uint(ap[4]);
                af[mt][3] = __float_as_uint(ap[8*36 + 4]);
            }
            #pragma unroll
            for (int nt = 0; nt < 4; nt++) {
                const float* bp = bs + (ks*8 + tg)*136 + wn*32 + nt*8 + group;
                bf[nt][0] = __float_as_uint(bp[0]);
                bf[nt][1] = __float_as_uint(bp[4*136]);
            }
            #pragma unroll
            for (int mt = 0; mt < 4; mt++)
                #pragma unroll
                for (int nt = 0; nt < 4; nt++)
                    mma16n8k8(acc[mt][nt], af[mt], bf[nt]);
        }
    }

    #pragma unroll
    for (int mt = 0; mt < 4; mt++) {
        int row = i0 + wm*64 + mt*16 + group;
        #pragma unroll
        for (int nt = 0; nt < 4; nt++) {
            int col = p0 + wn*32 + nt*8 + tg*2;
            *(float2*)&C[(size_t)row*PDIM + col]     = make_float2(acc[mt][nt][0], acc[mt][nt][1]);
            *(float2*)&C[(size_t)(row+8)*PDIM + col] = make_float2(acc[mt][nt][2], acc[mt][nt][3]);
        }
    }
}

// ============================================================
// K45: fused gate/out-projection + SwiGLU transition.
// REVERTED to R13/R14 structure (3 barriers/chunk, inline weight loads):
// R15's hoisted loads forced spills at the 128-reg cap.
// ============================================================
__global__ void __launch_bounds__(256,2) k45_mma(
    const float* __restrict__ m, const float* __restrict__ Wout,
    const float* __restrict__ lng, const float* __restrict__ lnb,
    const float* __restrict__ Wa, const float* __restrict__ Wb, const float* __restrict__ Wo,
    float* __restrict__ out)
{
    extern __shared__ float sh45[];
    float* stA  = sh45;              // [128][68]
    float* ovl  = sh45 + 128*68;     // overlay region: 11520 floats
    float* sx   = ovl;               // [128][68]
    float* shh  = ovl;               // [128][36]
    float* swab = ovl + 128*36;      // [64][72]
    float* swo  = ovl + 128*36 + 64*72;  // [32][72]
    float* sWout= sh45 + 128*68 + 11520; // [64][72]

    int tid = threadIdx.x, wid = tid >> 5, lane = tid & 31;
    int group = lane >> 2, tg = lane & 3;
    int wm = wid >> 2, wn = wid & 3;
    int wm2 = wid >> 1, wn2 = wid & 1;
    float gm0 = lng[lane], gm1 = lng[lane+32];
    float bt0 = lnb[lane], bt1 = lnb[lane+32];
    int wk = tid >> 2, wq = tid & 3;
    int wk2 = tid >> 3, wq2 = tid & 7;

    #pragma unroll
    for (int u = 0; u < 4; u++) {
        float4 w4 = *(const float4*)&Wout[(size_t)wk*64 + wq*16 + u*4];
        *(float4*)&sWout[wk*72 + wq*16 + u*4] =
            make_float4(tf32r(w4.x),tf32r(w4.y),tf32r(w4.z),tf32r(w4.w));
    }

    for (int tile = blockIdx.x; tile < NROWS/128; tile += gridDim.x) {
        int rbase = tile*128;
        int ss = rbase >> 9, ii0 = rbase & 511;

        #pragma unroll
        for (int i = 0; i < 8; i++) {
            int flat4 = i*256 + tid;
            int row = flat4 >> 4, c4 = flat4 & 15;
            int k0 = c4*4; int hh = k0 >> 3, cc = k0 & 7;
            float4 g4 = *(const float4*)&g_G[(size_t)(rbase+row)*64 + k0];
            float4 w4 = *(const float4*)&g_WV[((size_t)hh*N_DIM + ii0 + row)*PDIM + ss*8 + cc];
            *(float4*)&stA[row*68 + k0] = make_float4(
                tf32r(g4.x*w4.x), tf32r(g4.y*w4.y), tf32r(g4.z*w4.z), tf32r(g4.w*w4.w));
        }
        __syncthreads();

        float acc2[2][4][4] = {};
        #pragma unroll
        for (int ks = 0; ks < 8; ks++) {
            uint32_t af[2][4], bf[4][2];
            #pragma unroll
            for (int mt = 0; mt < 2; mt++) {
                const float* ap = stA + (wm2*32 + mt*16 + group)*68 + ks*8 + tg;
                af[mt][0] = __float_as_uint(ap[0]);
                af[mt][1] = __float_as_uint(ap[8*68]);
                af[mt][2] = __float_as_uint(ap[4]);
                af[mt][3] = __float_as_uint(ap[8*68 + 4]);
            }
            #pragma unroll
            for (int nt = 0; nt < 4; nt++) {
                const float* bp = sWout + (ks*8 + tg)*72 + wn2*32 + nt*8 + group;
                bf[nt][0] = __float_as_uint(bp[0]);
                bf[nt][1] = __float_as_uint(bp[4*72]);
            }
            #pragma unroll
            for (int mt = 0; mt < 2; mt++)
                #pragma unroll
                for (int nt = 0; nt < 4; nt++)
                    mma16n8k8(acc2[mt][nt], af[mt], bf[nt]);
        }
        #pragma unroll
        for (int mt = 0; mt < 2; mt++) {
            int row = rbase + wm2*32 + mt*16 + group;
            #pragma unroll
            for (int nt = 0; nt < 4; nt++) {
                int col = wn2*32 + nt*8 + tg*2;
                float2 m0 = *(const float2*)&m[(size_t)row*64 + col];
                acc2[mt][nt][0] += m0.x; acc2[mt][nt][1] += m0.y;
                float2 m1 = *(const float2*)&m[(size_t)(row+8)*64 + col];
                acc2[mt][nt][2] += m1.x; acc2[mt][nt][3] += m1.y;
            }
        }

        #pragma unroll
        for (int mt = 0; mt < 2; mt++) {
            int r1 = wm2*32 + mt*16 + group;
            #pragma unroll
            for (int nt = 0; nt < 4; nt++) {
                int col = wn2*32 + nt*8 + tg*2;
                *(float2*)&sx[r1*68 + col]     = make_float2(acc2[mt][nt][0], acc2[mt][nt][1]);
                *(float2*)&sx[(r1+8)*68 + col] = make_float2(acc2[mt][nt][2], acc2[mt][nt][3]);
            }
        }
        __syncthreads();

        #pragma unroll 1
        for (int rr = 0; rr < 16; rr += 4) {
            float xs0[4], xs1[4], s[4], q[4];
            #pragma unroll
            for (int u = 0; u < 4; u++) {
                int row = wid*16 + rr + u;
                xs0[u] = sx[row*68 + lane];
                xs1[u] = sx[row*68 + 32 + lane];
                s[u] = xs0[u] + xs1[u];
                q[u] = xs0[u]*xs0[u] + xs1[u]*xs1[u];
            }
            #pragma unroll
            for (int o = 16; o > 0; o >>= 1) {
                #pragma unroll
                for (int u = 0; u < 4; u++) {
                    s[u] += __shfl_xor_sync(0xffffffffu, s[u], o);
                    q[u] += __shfl_xor_sync(0xffffffffu, q[u], o);
                }
            }
            #pragma unroll
            for (int u = 0; u < 4; u++) {
                int row = wid*16 + rr + u;
                float mean = s[u]*(1.0f/64.0f);
                float var  = q[u]*(1.0f/64.0f) - mean*mean;
                float rs = rsqrtf(var + 1e-5f);
                stA[row*68 + lane]      = tf32r((xs0[u]-mean)*rs*gm0 + bt0);
                stA[row*68 + 32 + lane] = tf32r((xs1[u]-mean)*rs*gm1 + bt1);
            }
        }

        #pragma unroll 1
        for (int hc = 0; hc < 8; hc++) {
            __syncthreads();
            #pragma unroll
            for (int u = 0; u < 2; u++) {
                float4 a4 = *(const float4*)&Wa[(size_t)wk*256 + hc*32 + wq*8 + u*4];
                float4 b4 = *(const float4*)&Wb[(size_t)wk*256 + hc*32 + wq*8 + u*4];
                int base = wk*72 + wq*16 + u*8;
                swab[base+0] = tf32r(a4.x); swab[base+1] = tf32r(b4.x);
                swab[base+2] = tf32r(a4.y); swab[base+3] = tf32r(b4.y);
                swab[base+4] = tf32r(a4.z); swab[base+5] = tf32r(b4.z);
                swab[base+6] = tf32r(a4.w); swab[base+7] = tf32r(b4.w);
                float4 o4 = *(const float4*)&Wo[(size_t)(hc*32 + wk2)*64 + wq2*8 + u*4];
                *(float4*)&swo[wk2*72 + wq2*8 + u*4] =
                    make_float4(tf32r(o4.x), tf32r(o4.y), tf32r(o4.z), tf32r(o4.w));
            }
            __syncthreads();
            float acc1[4][2][4] = {};
            #pragma unroll
            for (int ks = 0; ks < 8; ks++) {
                uint32_t af[4][4], bf[2][2];
                #pragma unroll
                for (int mt = 0; mt < 4; mt++) {
                    const float* ap = stA + (wm*64 + mt*16 + group)*68 + ks*8 + tg;
                    af[mt][0] = __float_as_uint(ap[0]);
                    af[mt][1] = __float_as_uint(ap[8*68]);
                    af[mt][2] = __float_as_uint(ap[4]);
                    af[mt][3] = __float_as_uint(ap[8*68 + 4]);
                }
                #pragma unroll
                for (int nt = 0; nt < 2; nt++) {
                    const float* bp = swab + (ks*8 + tg)*72 + wn*16 + nt*8 + group;
                    bf[nt][0] = __float_as_uint(bp[0]);
                    bf[nt][1] = __float_as_uint(bp[4*72]);
                }
                #pragma unroll
                for (int mt = 0; mt < 4; mt++)
                    #pragma unroll
                    for (int nt = 0; nt < 2; nt++)
                        mma16n8k8(acc1[mt][nt], af[mt], bf[nt]);
            }
            #pragma unroll
            for (int mt = 0; mt < 4; mt++) {
                int r1 = wm*64 + mt*16 + group;
                #pragma unroll
                for (int nt = 0; nt < 2; nt++) {
                    int hcol = wn*8 + nt*4 + tg;
                    float a0 = acc1[mt][nt][0], b0v = acc1[mt][nt][1];
                    float a1 = acc1[mt][nt][2], b1v = acc1[mt][nt][3];
                    float h0 = __fdividef(a0, 1.0f + __expf(-a0)) * b0v;
                    float h1 = __fdividef(a1, 1.0f + __expf(-a1)) * b1v;
                    shh[r1*36 + hcol]      = tf32r(h0);
                    shh[(r1+8)*36 + hcol]  = tf32r(h1);
                }
            }
            __syncthreads();
            #pragma unroll
            for (int ks = 0; ks < 4; ks++) {
                uint32_t af[2][4], bf[4][2];
                #pragma unroll
                for (int mt = 0; mt < 2; mt++) {
                    const float* ap = shh + (wm2*32 + mt*16 + group)*36 + ks*8 + tg;
                    af[mt][0] = __float_as_uint(ap[0]);
                    af[mt][1] = __float_as_uint(ap[8*36]);
                    af[mt][2] = __float_as_uint(ap[4]);
                    af[mt][3] = __float_as_uint(ap[8*36 + 4]);
                }
                #pragma unroll
                for (int nt = 0; nt < 4; nt++) {
                    const float* bp = swo + (ks*8 + tg)*72 + wn2*32 + nt*8 + group;
                    bf[nt][0] = __float_as_uint(bp[0]);
                    bf[nt][1] = __float_as_uint(bp[4*72]);
                }
                #pragma unroll
                for (int mt = 0; mt < 2; mt++)
                    #pragma unroll
                    for (int nt = 0; nt < 4; nt++)
                        mma16n8k8(acc2[mt][nt], af[mt], bf[nt]);
            }
        }
        #pragma unroll
        for (int mt = 0; mt < 2; mt++) {
            int row = rbase + wm2*32 + mt*16 + group;
            #pragma unroll
            for (int nt = 0; nt < 4; nt++) {
                int col = wn2*32 + nt*8 + tg*2;
                *(float2*)&out[(size_t)row*64 + col] =
                    make_float2(acc2[mt][nt][0], acc2[mt][nt][1]);
                *(float2*)&out[(size_t)(row+8)*64 + col] =
                    make_float2(acc2[mt][nt][2], acc2[mt][nt][3]);
            }
        }
        __syncthreads();
    }
}

// ============================================================
extern "C" void kernel_launch(void* const* d_in, const int* in_sizes, int n_in,
                              void* d_out, int out_size) {
    const float* m    = (const float*)d_in[0];
    const float* z    = (const float*)d_in[1];
    const float* lnmg = (const float*)d_in[2];
    const float* lnmb = (const float*)d_in[3];
    const float* Wmv  = (const float*)d_in[4];
    const float* lnzg = (const float*)d_in[5];
    const float* lnzb = (const float*)d_in[6];
    const float* Wz   = (const float*)d_in[7];
    const float* Wmg  = (const float*)d_in[8];
    const float* Wout = (const float*)d_in[9];
    const float* lntg = (const float*)d_in[10];
    const float* lntb = (const float*)d_in[11];
    const float* Wa   = (const float*)d_in[12];
    const float* Wb   = (const float*)d_in[13];
    const float* Wo   = (const float*)d_in[14];
    float* out = (float*)d_out;

    const int k1_smem = (128*68 + 64*136) * 4;       // 69,632 B
    cudaFuncSetAttribute(k1_mma, cudaFuncAttributeMaxDynamicSharedMemorySize, k1_smem);
    k1_mma<<<NROWS/128, 256, k1_smem>>>(m, lnmg, lnmb, Wmv, Wmg);

    k2_fused<<<N_DIM, 256>>>(z, lnzg, lnzb, Wz);

    const int k3_smem = 3*(4608 + 4352) * 4;         // 107,520 B
    cudaFuncSetAttribute(k3_mma, cudaFuncAttributeMaxDynamicSharedMemorySize, k3_smem);
    k3_mma<<<dim3(PDIM/128, N_DIM/128, HH), 256, k3_smem>>>();

    const int k45_smem = (128*68 + 11520 + 64*72) * 4;   // 99,328 B
    cudaFuncSetAttribute(k45_mma, cudaFuncAttributeMaxDynamicSharedMemorySize, k45_smem);
    k45_mma<<<296, 256, k45_smem>>>(m, Wout, lntg, lntb, Wa, Wb, Wo, out);
    (void)in_sizes; (void)n_in; (void)out_size;
}